// round 13
// baseline (speedup 1.0000x reference)
#include <cuda_runtime.h>
#include <cuda_fp16.h>

// Problem constants
#define NB   2
#define LL   2048
#define DD   1024
#define HH   16
#define DH   64
#define NHB  (NB*HH)                  // 32
#define NLD  (NB*LL*DD)               // 4194304
#define KP   72                       // smem pitch in halves (144B rows: ldmatrix conflict-free)
#define QSPLIT 4
#define TILEH (128*KP)                // halves per 128x64 smem tile

// logits = energy / sqrt(1024); base-2: exp(x/32) = exp2(x * log2(e)/32)
__device__ __constant__ float S2c = 1.44269504088896340736f / 32.0f;

// ---------------- scratch (device globals; no allocations allowed) ----------------
__device__ __half g_vh [NLD];
__device__ __half g_kh [NLD];
__device__ __half g_qh [NLD];
__device__ __half g_ovh[NLD];
__device__ __half g_okh[NLD];
__device__ __half g_fwh[DD*DD];
__device__ __half g_Xh [NLD];
__device__ float  g_samp  [NHB*LL];
__device__ float  g_lse2  [NHB*LL];
__device__ float  g_colpart[QSPLIT*NHB*LL];
// unnormalized scores, q-major: g_P[nh][q][l] = exp2(e[q,l]*S2), fp16 (lower triangle used)
__device__ __half g_P[(size_t)NHB * LL * LL];   // 268 MB

// ---------------- helpers ----------------
__device__ __forceinline__ unsigned sptr(const void* p) {
    return (unsigned)__cvta_generic_to_shared(p);
}
__device__ __forceinline__ void ldsm4(unsigned r[4], unsigned a) {
    asm volatile("ldmatrix.sync.aligned.m8n8.x4.shared.b16 {%0,%1,%2,%3}, [%4];"
        : "=r"(r[0]), "=r"(r[1]), "=r"(r[2]), "=r"(r[3]) : "r"(a));
}
__device__ __forceinline__ void hmma(float c[4], const unsigned a[4], const unsigned b[2]) {
    asm volatile("mma.sync.aligned.m16n8k16.row.col.f32.f16.f16.f32 "
        "{%0,%1,%2,%3},{%4,%5,%6,%7},{%8,%9},{%0,%1,%2,%3};"
        : "+f"(c[0]), "+f"(c[1]), "+f"(c[2]), "+f"(c[3])
        : "r"(a[0]), "r"(a[1]), "r"(a[2]), "r"(a[3]), "r"(b[0]), "r"(b[1]));
}
__device__ __forceinline__ uint4 cvt8(float4 f0, float4 f1) {
    __half2 h[4] = { __floats2half2_rn(f0.x, f0.y), __floats2half2_rn(f0.z, f0.w),
                     __floats2half2_rn(f1.x, f1.y), __floats2half2_rn(f1.z, f1.w) };
    return *reinterpret_cast<uint4*>(h);
}
__device__ __forceinline__ float ex2(float x) {
    float r; asm("ex2.approx.f32 %0, %1;" : "=f"(r) : "f"(x)); return r;
}
__device__ __forceinline__ void cpa16(__half* dst, const __half* src) {
    asm volatile("cp.async.cg.shared.global [%0], [%1], 16;"
        :: "r"(sptr(dst)), "l"(src));
}
#define CP_COMMIT() asm volatile("cp.async.commit_group;")
#define CP_WAIT0()  asm volatile("cp.async.wait_group 0;")
#define CP_WAIT1()  asm volatile("cp.async.wait_group 1;")

// cp.async a 128x64-half tile (row stride srow halves) into [.][KP] smem
__device__ __forceinline__ void
cp_tile(__half* dst, const __half* src, int tid)
{
#pragma unroll
    for (int t = 0; t < 4; ++t) {
        int u = tid + t * 256;                 // 1024 units of 8 halves
        int m = u >> 3, d8 = u & 7;
        cpa16(dst + m * KP + d8 * 8, src + (size_t)m * 1024 + d8 * 8);
    }
}

// A-operand ldmatrix address for a 16x16 tile at (row0, k0) in [.][KP] smem
__device__ __forceinline__ unsigned a_addr(unsigned base, int row0, int k0, int lane) {
    return base + (unsigned)(((row0 + (lane & 15)) * KP + k0 + ((lane >> 4) << 3)) * 2);
}
// B-operand pair address (2 adjacent n-tiles = 16 n-rows) at (n0, k0)
__device__ __forceinline__ unsigned b_addr(unsigned base, int n0, int k0, int lane) {
    int g = lane & 7, sel = lane >> 3;
    return base + (unsigned)(((n0 + g + ((sel >> 1) << 3)) * KP + k0 + ((sel & 1) << 3)) * 2);
}

// ============================================================================
// 1) Fused projections + fc_w convert. grid (256, 6); block 256.
//    y<5: out = X @ W^T (65536 x 64 x 64), fp16 HMMA. y==5: fc_w -> fp16.
// ============================================================================
__global__ void __launch_bounds__(256)
proj_kernel(const float* __restrict__ v_in, const float* __restrict__ k_in,
            const float* __restrict__ q_in, const float* __restrict__ ov_in,
            const float* __restrict__ ok_in,
            const float* __restrict__ Wv, const float* __restrict__ Wk,
            const float* __restrict__ Wq, const float* __restrict__ fw)
{
    __shared__ __half As[256 * KP];
    __shared__ __half Ws[64 * KP];

    const int tid = threadIdx.x;
    if (blockIdx.y == 5) {                    // fc_w fp32 -> fp16, 512 units of 8
        int u0 = blockIdx.x * 512;
#pragma unroll
        for (int t = 0; t < 2; ++t) {
            int u = u0 + tid + t * 256;
            float4 f0 = *reinterpret_cast<const float4*>(fw + (size_t)u * 8);
            float4 f1 = *reinterpret_cast<const float4*>(fw + (size_t)u * 8 + 4);
            *reinterpret_cast<uint4*>(g_fwh + (size_t)u * 8) = cvt8(f0, f1);
        }
        return;
    }

    const float* X; const float* W; __half* out;
    switch (blockIdx.y) {
        case 0:  X = v_in;  W = Wv; out = g_vh;  break;
        case 1:  X = k_in;  W = Wk; out = g_kh;  break;
        case 2:  X = q_in;  W = Wq; out = g_qh;  break;
        case 3:  X = ov_in; W = Wv; out = g_ovh; break;
        default: X = ok_in; W = Wk; out = g_okh; break;
    }
    const size_t r0 = (size_t)blockIdx.x * 256;
    const float* Xb = X + r0 * 64;

#pragma unroll
    for (int t = 0; t < 8; ++t) {
        int u = tid + t * 256;                 // 2048 units of 8 halves
        int m = u >> 3, d8 = u & 7;
        float4 f0 = *reinterpret_cast<const float4*>(Xb + m * 64 + d8 * 8);
        float4 f1 = *reinterpret_cast<const float4*>(Xb + m * 64 + d8 * 8 + 4);
        *reinterpret_cast<uint4*>(As + m * KP + d8 * 8) = cvt8(f0, f1);
    }
#pragma unroll
    for (int t = 0; t < 2; ++t) {
        int u = tid + t * 256;                 // 512 units
        int m = u >> 3, d8 = u & 7;
        float4 f0 = *reinterpret_cast<const float4*>(W + m * 64 + d8 * 8);
        float4 f1 = *reinterpret_cast<const float4*>(W + m * 64 + d8 * 8 + 4);
        *reinterpret_cast<uint4*>(Ws + m * KP + d8 * 8) = cvt8(f0, f1);
    }
    __syncthreads();

    const int warp = tid >> 5, lane = tid & 31;
    const int wm = warp >> 1, wn = warp & 1;   // m: 4x64, n: 2x32
    const unsigned aB = sptr(As), wB = sptr(Ws);

    float c[4][4][4] = {};
#pragma unroll
    for (int kk = 0; kk < 4; ++kk) {
        const int k0 = kk * 16;
        unsigned a[4][4], b[4][2];
#pragma unroll
        for (int mt = 0; mt < 4; ++mt)
            ldsm4(a[mt], a_addr(aB, wm * 64 + mt * 16, k0, lane));
#pragma unroll
        for (int p = 0; p < 2; ++p) {
            unsigned r[4];
            ldsm4(r, b_addr(wB, wn * 32 + p * 16, k0, lane));
            b[2*p][0] = r[0]; b[2*p][1] = r[1];
            b[2*p+1][0] = r[2]; b[2*p+1][1] = r[3];
        }
#pragma unroll
        for (int mt = 0; mt < 4; ++mt)
#pragma unroll
            for (int nt = 0; nt < 4; ++nt)
                hmma(c[mt][nt], a[mt], b[nt]);
    }

#pragma unroll
    for (int mt = 0; mt < 4; ++mt) {
        int rr = wm * 64 + mt * 16 + (lane >> 2);
#pragma unroll
        for (int nt = 0; nt < 4; ++nt) {
            int cc = wn * 32 + nt * 8 + 2 * (lane & 3);
            *reinterpret_cast<__half2*>(out + (r0 + rr) * 64 + cc) =
                __floats2half2_rn(c[mt][nt][0], c[mt][nt][1]);
            *reinterpret_cast<__half2*>(out + (r0 + rr + 8) * 64 + cc) =
                __floats2half2_rn(c[mt][nt][2], c[mt][nt][3]);
        }
    }
}

// ============================================================================
// 2) Pass 1: HMMA QK^T, cp.async double-buffered; computes samp (diag energies)
//    in-kernel; per-row log2-sum-exp (diag -> samp); stores P fp16 q-major.
//    dynamic smem: qs + 2 x ks = 3 * TILEH halves.
// ============================================================================
__global__ void __launch_bounds__(256, 2)
pass1_kernel()
{
    extern __shared__ __half dsm[];
    __half* qs  = dsm;
    __half* ks0 = dsm + TILEH;
    __half* ks1 = dsm + 2 * TILEH;
    __shared__ float sampS[128];
    __shared__ float rowsum[4 * 128];

    const int tid = threadIdx.x, warp = tid >> 5, lane = tid & 31;
    const int wm = warp >> 2, wn = warp & 3;          // m: 2x64, n: 4x32
    const int nh = blockIdx.y, n = nh >> 4, h = nh & 15;
    const int qblk = 15 - blockIdx.x;                 // longest blocks first
    const int q0 = qblk * 128;
    const size_t baseh = (size_t)n * LL * HH * DH + (size_t)h * DH;
    const size_t pbase = (size_t)nh * LL * LL;
    const float S2 = S2c;

    // async prologue: q tile -> qs, ok tile 0 -> ks0, k tile (for samp) -> ks1
    cp_tile(qs,  g_qh  + baseh + (size_t)q0 * 1024, tid); CP_COMMIT();
    cp_tile(ks0, g_okh + baseh,                     tid); CP_COMMIT();
    cp_tile(ks1, g_kh  + baseh + (size_t)q0 * 1024, tid); CP_COMMIT();
    CP_WAIT0();
    __syncthreads();

    // samp energies for this block's 128 q rows (dot of q,k from smem)
    if (tid < 128) {
        const __half2* qr = reinterpret_cast<const __half2*>(qs  + tid * KP);
        const __half2* kr = reinterpret_cast<const __half2*>(ks1 + tid * KP);
        float s = 0.0f;
#pragma unroll
        for (int i = 0; i < 32; ++i) {
            float2 a = __half22float2(qr[i]);
            float2 b = __half22float2(kr[i]);
            s += a.x * b.x + a.y * b.y;
        }
        sampS[tid] = s;
        g_samp[nh * LL + q0 + tid] = s;
    }

    const unsigned qB = sptr(qs);
    float srun[4][2] = {};                            // [mt][row-half]

    for (int ct = 0; ct <= qblk; ++ct) {
        __syncthreads();      // prior reads of target buffer (incl. samp) complete
        if (ct + 1 <= qblk) { // prefetch next ok tile
            __half* nb = ((ct + 1) & 1) ? ks1 : ks0;
            cp_tile(nb, g_okh + baseh + (size_t)(ct + 1) * 128 * 1024, tid);
            CP_COMMIT();
            CP_WAIT1();       // current tile's group complete (newest may pend)
        } else {
            CP_WAIT0();
        }
        __syncthreads();

        const unsigned kB = sptr((ct & 1) ? ks1 : ks0);

        float c[4][4][4] = {};
#pragma unroll
        for (int kk = 0; kk < 4; ++kk) {
            const int k0 = kk * 16;
            unsigned a[4][4], b[4][2];
#pragma unroll
            for (int mt = 0; mt < 4; ++mt)
                ldsm4(a[mt], a_addr(qB, wm * 64 + mt * 16, k0, lane));
#pragma unroll
            for (int p = 0; p < 2; ++p) {
                unsigned r[4];
                ldsm4(r, b_addr(kB, wn * 32 + p * 16, k0, lane));
                b[2*p][0] = r[0]; b[2*p][1] = r[1];
                b[2*p+1][0] = r[2]; b[2*p+1][1] = r[3];
            }
#pragma unroll
            for (int mt = 0; mt < 4; ++mt)
#pragma unroll
                for (int nt = 0; nt < 4; ++nt)
                    hmma(c[mt][nt], a[mt], b[nt]);
        }

        const bool dt = (ct == qblk);
        const int l0 = ct * 128;
#pragma unroll
        for (int mt = 0; mt < 4; ++mt) {
            const int rA = wm * 64 + mt * 16 + (lane >> 2);   // local q row (c0,c1)
            const int rB = rA + 8;                            // local q row (c2,c3)
#pragma unroll
            for (int nt = 0; nt < 4; ++nt) {
                const int cl = wn * 32 + nt * 8 + 2 * (lane & 3);   // local l col
                float p0 = ex2(c[mt][nt][0] * S2);
                float p1 = ex2(c[mt][nt][1] * S2);
                float p2 = ex2(c[mt][nt][2] * S2);
                float p3 = ex2(c[mt][nt][3] * S2);
                *reinterpret_cast<__half2*>(g_P + pbase + (size_t)(q0 + rA) * LL + l0 + cl) =
                    __floats2half2_rn(p0, p1);
                *reinterpret_cast<__half2*>(g_P + pbase + (size_t)(q0 + rB) * LL + l0 + cl) =
                    __floats2half2_rn(p2, p3);
                if (dt) {
                    if (cl     < rA) srun[mt][0] += p0;
                    else if (cl     == rA) srun[mt][0] += ex2(sampS[rA] * S2);
                    if (cl + 1 < rA) srun[mt][0] += p1;
                    else if (cl + 1 == rA) srun[mt][0] += ex2(sampS[rA] * S2);
                    if (cl     < rB) srun[mt][1] += p2;
                    else if (cl     == rB) srun[mt][1] += ex2(sampS[rB] * S2);
                    if (cl + 1 < rB) srun[mt][1] += p3;
                    else if (cl + 1 == rB) srun[mt][1] += ex2(sampS[rB] * S2);
                } else {
                    srun[mt][0] += p0 + p1;
                    srun[mt][1] += p2 + p3;
                }
            }
        }
    }

    // deterministic block reduction: lane-quad reduce, per-wn smem slot, final sum
#pragma unroll
    for (int mt = 0; mt < 4; ++mt)
#pragma unroll
        for (int hf = 0; hf < 2; ++hf) {
            float s = srun[mt][hf];
            s += __shfl_xor_sync(0xffffffffu, s, 1);
            s += __shfl_xor_sync(0xffffffffu, s, 2);
            if ((lane & 3) == 0)
                rowsum[wn * 128 + wm * 64 + mt * 16 + (lane >> 2) + hf * 8] = s;
        }
    __syncthreads();
    if (tid < 128) {
        float s = rowsum[tid] + rowsum[128 + tid] + rowsum[256 + tid] + rowsum[384 + tid];
        g_lse2[nh * LL + q0 + tid] = log2f(s);
    }
}

// ============================================================================
// 3) colsum partials: colpart[part][nh][l] = sum_{q in slice, q>l} P[q][l]*2^-lse2[q]
// ============================================================================
__global__ void __launch_bounds__(256)
colsum_kernel()
{
    __shared__ float w[LL];
    const int nh = blockIdx.y, tid = threadIdx.x;
    for (int i = tid; i < LL; i += 256) w[i] = ex2(-g_lse2[nh * LL + i]);
    __syncthreads();

    const int l0 = blockIdx.x * 512;
    const int l = l0 + tid * 2;
    const int part = blockIdx.z;
    const int span = LL - l0;
    int qa = l0 + (span * part) / QSPLIT;
    int qb = l0 + (span * (part + 1)) / QSPLIT;
    if (qa < l0 + 1) qa = l0 + 1;

    const __half* base = g_P + (size_t)nh * LL * LL;
    float s0 = 0.0f, s1 = 0.0f;
#pragma unroll 8
    for (int q = qa; q < qb; ++q) {
        float2 f = __half22float2(*reinterpret_cast<const __half2*>(base + (size_t)q * LL + l));
        float wq = w[q];
        if (q > l)     s0 += f.x * wq;
        if (q > l + 1) s1 += f.y * wq;
    }
    float* dst = g_colpart + ((size_t)part * NHB + nh) * LL;
    dst[l]     = s0;
    dst[l + 1] = s1;
}

// ============================================================================
// 4) Combine: X[n,l,h,:] = diag_score * v + colsum * ov   (half in/out)
// ============================================================================
__global__ void __launch_bounds__(256)
combine_kernel()
{
    int u = blockIdx.x * 256 + threadIdx.x;          // unit of 8 halves
    int hidx = u >> 3;                                // (n*LL + l)*HH + h
    int h = hidx & 15;
    int nl = hidx >> 4;
    int l = nl & (LL - 1);
    int n = nl >> 11;
    int si = (n * HH + h) * LL + l;
    float dg = ex2(g_samp[si] * S2c - g_lse2[si]);
    float cs = g_colpart[si] + g_colpart[NHB * LL + si]
             + g_colpart[2 * NHB * LL + si] + g_colpart[3 * NHB * LL + si];

    uint4 v4 = *reinterpret_cast<const uint4*>(g_vh  + (size_t)u * 8);
    uint4 o4 = *reinterpret_cast<const uint4*>(g_ovh + (size_t)u * 8);
    __half2* vh = reinterpret_cast<__half2*>(&v4);
    __half2* oh = reinterpret_cast<__half2*>(&o4);
    __half2 r[4];
#pragma unroll
    for (int i = 0; i < 4; ++i) {
        float2 fv = __half22float2(vh[i]);
        float2 fo = __half22float2(oh[i]);
        r[i] = __floats2half2_rn(dg * fv.x + cs * fo.x, dg * fv.y + cs * fo.y);
    }
    *reinterpret_cast<uint4*>(g_Xh + (size_t)u * 8) = *reinterpret_cast<uint4*>(r);
}

// ============================================================================
// 5) FC: out = X @ fc_w^T + fc_b  (4096x1024x1024), fp16 HMMA, cp.async 2-stage
//    dynamic smem: 4 x TILEH halves (A0,B0,A1,B1)
// ============================================================================
__global__ void __launch_bounds__(256, 2)
fc_kernel(const float* __restrict__ bias, float* __restrict__ out)
{
    extern __shared__ __half dsm[];
    __half* Ab[2] = { dsm,             dsm + 2 * TILEH };
    __half* Bb[2] = { dsm + TILEH,     dsm + 3 * TILEH };

    const int tid = threadIdx.x, warp = tid >> 5, lane = tid & 31;
    const int wm = warp >> 2, wn = warp & 3;          // m: 2x64, n: 4x32
    const int m0 = blockIdx.y * 128, j0 = blockIdx.x * 128;

    // stage 0
    cp_tile(Ab[0], g_Xh  + (size_t)m0 * 1024, tid);
    cp_tile(Bb[0], g_fwh + (size_t)j0 * 1024, tid);
    CP_COMMIT();

    float c[4][4][4] = {};
    for (int it = 0; it < 16; ++it) {
        __syncthreads();                 // reads of target buffer complete
        if (it + 1 < 16) {
            int nb = (it + 1) & 1;
            cp_tile(Ab[nb], g_Xh  + (size_t)m0 * 1024 + (it + 1) * 64, tid);
            cp_tile(Bb[nb], g_fwh + (size_t)j0 * 1024 + (it + 1) * 64, tid);
            CP_COMMIT();
            CP_WAIT1();
        } else {
            CP_WAIT0();
        }
        __syncthreads();

        const unsigned aB = sptr(Ab[it & 1]), bB = sptr(Bb[it & 1]);
#pragma unroll
        for (int kk = 0; kk < 4; ++kk) {
            const int k0 = kk * 16;
            unsigned a[4][4], b[4][2];
#pragma unroll
            for (int mt = 0; mt < 4; ++mt)
                ldsm4(a[mt], a_addr(aB, wm * 64 + mt * 16, k0, lane));
#pragma unroll
            for (int p = 0; p < 2; ++p) {
                unsigned r[4];
                ldsm4(r, b_addr(bB, wn * 32 + p * 16, k0, lane));
                b[2*p][0] = r[0]; b[2*p][1] = r[1];
                b[2*p+1][0] = r[2]; b[2*p+1][1] = r[3];
            }
#pragma unroll
            for (int mt = 0; mt < 4; ++mt)
#pragma unroll
                for (int nt = 0; nt < 4; ++nt)
                    hmma(c[mt][nt], a[mt], b[nt]);
        }
    }

#pragma unroll
    for (int mt = 0; mt < 4; ++mt) {
        int rr = m0 + wm * 64 + mt * 16 + (lane >> 2);
#pragma unroll
        for (int nt = 0; nt < 4; ++nt) {
            int cc = j0 + wn * 32 + nt * 8 + 2 * (lane & 3);
            float2 bb = *reinterpret_cast<const float2*>(bias + cc);
            *reinterpret_cast<float2*>(out + (size_t)rr * 1024 + cc) =
                make_float2(c[mt][nt][0] + bb.x, c[mt][nt][1] + bb.y);
            *reinterpret_cast<float2*>(out + (size_t)(rr + 8) * 1024 + cc) =
                make_float2(c[mt][nt][2] + bb.x, c[mt][nt][3] + bb.y);
        }
    }
}

// ============================================================================
extern "C" void kernel_launch(void* const* d_in, const int* in_sizes, int n_in,
                              void* d_out, int out_size)
{
    const float* values        = (const float*)d_in[0];
    const float* keys          = (const float*)d_in[1];
    const float* query         = (const float*)d_in[2];
    const float* origin_values = (const float*)d_in[3];
    const float* origin_keys   = (const float*)d_in[4];
    const float* Wv            = (const float*)d_in[5];
    const float* Wk            = (const float*)d_in[6];
    const float* Wq            = (const float*)d_in[7];
    const float* fc_w          = (const float*)d_in[8];
    const float* fc_b          = (const float*)d_in[9];
    // d_in[10] = mask : causal-only for these shapes (HIST == L); computed analytically.
    float* out = (float*)d_out;

    const int smem_p1 = 3 * TILEH * (int)sizeof(__half);   // 55296 B
    const int smem_fc = 4 * TILEH * (int)sizeof(__half);   // 73728 B
    cudaFuncSetAttribute(pass1_kernel, cudaFuncAttributeMaxDynamicSharedMemorySize, smem_p1);
    cudaFuncSetAttribute(fc_kernel,    cudaFuncAttributeMaxDynamicSharedMemorySize, smem_fc);

    // 1) fused projections (5 tensors) + fc_w convert
    proj_kernel<<<dim3(256, 6), 256>>>(values, keys, query, origin_values, origin_keys,
                                       Wv, Wk, Wq, fc_w);

    // 2) row log2-sum-exp (diag replaced, samp computed in-kernel) + store P
    pass1_kernel<<<dim3(16, NHB), 256, smem_p1>>>();

    // 3) weighted column-sum partials of stored scores (strictly below diagonal)
    colsum_kernel<<<dim3(LL / 512, NHB, QSPLIT), 256>>>();

    // 4) combine samp + origin attention -> X (fp16)
    combine_kernel<<<NLD / 8 / 256, 256>>>();

    // 5) final linear layer (fp16 HMMA, fp32 out)
    fc_kernel<<<dim3(8, 32), 256, smem_fc>>>(fc_b, out);
}

// round 15
// speedup vs baseline: 1.3343x; 1.3343x over previous
#include <cuda_runtime.h>
#include <cuda_fp16.h>

// Problem constants
#define NB   2
#define LL   2048
#define DD   1024
#define HH   16
#define DH   64
#define NHB  (NB*HH)                  // 32
#define NLD  (NB*LL*DD)               // 4194304
#define KP   72                       // smem pitch in halves (144B rows: ldmatrix conflict-free)
#define TILEH (128*KP)                // halves per 128x64 smem tile
#define NTRI  136                     // 16*17/2 tiles per (n,h) triangle
#define TILE16K 16384                 // halves per 128x128 P tile (128*128)

// logits = energy / sqrt(1024); base-2: exp(x/32) = exp2(x * log2(e)/32)
__device__ __constant__ float S2c = 1.44269504088896340736f / 32.0f;

// ---------------- scratch (device globals; no allocations allowed) ----------------
__device__ __half g_vh [NLD];
__device__ __half g_kh [NLD];
__device__ __half g_qh [NLD];
__device__ __half g_ovh[NLD];
__device__ __half g_okh[NLD];
__device__ __half g_fwh[DD*DD];
__device__ __half g_Xh [NLD];
__device__ float  g_samp  [NHB*LL];
__device__ float  g_lse2  [NHB*LL];
__device__ float  g_colsum[NHB*LL];
// unnormalized scores P = exp2(e*S2), fp16, fragment-native tile layout,
// triangular tile packing: tile (qblk, ct) of head nh at
//   g_P + (nh*NTRI + qblk*(qblk+1)/2 + ct) * TILE16K
// within a tile: slot (warp*4 + mt) of 512 halves;
//   pk0 (nt0,1) at slot*512 + lane*8 ; pk1 (nt2,3) at slot*512 + 256 + lane*8
__device__ __half g_P[(size_t)NHB * NTRI * TILE16K];   // 142.6 MB

// ---------------- helpers ----------------
__device__ __forceinline__ unsigned sptr(const void* p) {
    return (unsigned)__cvta_generic_to_shared(p);
}
__device__ __forceinline__ void ldsm4(unsigned r[4], unsigned a) {
    asm volatile("ldmatrix.sync.aligned.m8n8.x4.shared.b16 {%0,%1,%2,%3}, [%4];"
        : "=r"(r[0]), "=r"(r[1]), "=r"(r[2]), "=r"(r[3]) : "r"(a));
}
__device__ __forceinline__ void hmma(float c[4], const unsigned a[4], const unsigned b[2]) {
    asm volatile("mma.sync.aligned.m16n8k16.row.col.f32.f16.f16.f32 "
        "{%0,%1,%2,%3},{%4,%5,%6,%7},{%8,%9},{%0,%1,%2,%3};"
        : "+f"(c[0]), "+f"(c[1]), "+f"(c[2]), "+f"(c[3])
        : "r"(a[0]), "r"(a[1]), "r"(a[2]), "r"(a[3]), "r"(b[0]), "r"(b[1]));
}
__device__ __forceinline__ uint4 cvt8(float4 f0, float4 f1) {
    __half2 h[4] = { __floats2half2_rn(f0.x, f0.y), __floats2half2_rn(f0.z, f0.w),
                     __floats2half2_rn(f1.x, f1.y), __floats2half2_rn(f1.z, f1.w) };
    return *reinterpret_cast<uint4*>(h);
}
__device__ __forceinline__ float ex2(float x) {
    float r; asm("ex2.approx.f32 %0, %1;" : "=f"(r) : "f"(x)); return r;
}
__device__ __forceinline__ void cpa16(__half* dst, const __half* src) {
    asm volatile("cp.async.cg.shared.global [%0], [%1], 16;"
        :: "r"(sptr(dst)), "l"(src));
}
#define CP_COMMIT() asm volatile("cp.async.commit_group;")
#define CP_WAIT0()  asm volatile("cp.async.wait_group 0;")
#define CP_WAIT1()  asm volatile("cp.async.wait_group 1;")

// cp.async a 128x64-half tile (global row stride 1024 halves) into [.][KP] smem
__device__ __forceinline__ void
cp_tile(__half* dst, const __half* src, int tid)
{
#pragma unroll
    for (int t = 0; t < 4; ++t) {
        int u = tid + t * 256;                 // 1024 units of 8 halves
        int m = u >> 3, d8 = u & 7;
        cpa16(dst + m * KP + d8 * 8, src + (size_t)m * 1024 + d8 * 8);
    }
}

// A-operand ldmatrix address for a 16x16 tile at (row0, k0) in [.][KP] smem
__device__ __forceinline__ unsigned a_addr(unsigned base, int row0, int k0, int lane) {
    return base + (unsigned)(((row0 + (lane & 15)) * KP + k0 + ((lane >> 4) << 3)) * 2);
}
// B-operand pair address (2 adjacent n-tiles = 16 n-rows) at (n0, k0)
__device__ __forceinline__ unsigned b_addr(unsigned base, int n0, int k0, int lane) {
    int g = lane & 7, sel = lane >> 3;
    return base + (unsigned)(((n0 + g + ((sel >> 1) << 3)) * KP + k0 + ((sel & 1) << 3)) * 2);
}

// ============================================================================
// 1) Fused projections + fc_w convert. grid (256, 6); block 256.
// ============================================================================
__global__ void __launch_bounds__(256)
proj_kernel(const float* __restrict__ v_in, const float* __restrict__ k_in,
            const float* __restrict__ q_in, const float* __restrict__ ov_in,
            const float* __restrict__ ok_in,
            const float* __restrict__ Wv, const float* __restrict__ Wk,
            const float* __restrict__ Wq, const float* __restrict__ fw)
{
    __shared__ __half As[256 * KP];
    __shared__ __half Ws[64 * KP];

    const int tid = threadIdx.x;
    if (blockIdx.y == 5) {                    // fc_w fp32 -> fp16
        int u0 = blockIdx.x * 512;
#pragma unroll
        for (int t = 0; t < 2; ++t) {
            int u = u0 + tid + t * 256;
            float4 f0 = *reinterpret_cast<const float4*>(fw + (size_t)u * 8);
            float4 f1 = *reinterpret_cast<const float4*>(fw + (size_t)u * 8 + 4);
            *reinterpret_cast<uint4*>(g_fwh + (size_t)u * 8) = cvt8(f0, f1);
        }
        return;
    }

    const float* X; const float* W; __half* out;
    switch (blockIdx.y) {
        case 0:  X = v_in;  W = Wv; out = g_vh;  break;
        case 1:  X = k_in;  W = Wk; out = g_kh;  break;
        case 2:  X = q_in;  W = Wq; out = g_qh;  break;
        case 3:  X = ov_in; W = Wv; out = g_ovh; break;
        default: X = ok_in; W = Wk; out = g_okh; break;
    }
    const size_t r0 = (size_t)blockIdx.x * 256;
    const float* Xb = X + r0 * 64;

#pragma unroll
    for (int t = 0; t < 8; ++t) {
        int u = tid + t * 256;
        int m = u >> 3, d8 = u & 7;
        float4 f0 = *reinterpret_cast<const float4*>(Xb + m * 64 + d8 * 8);
        float4 f1 = *reinterpret_cast<const float4*>(Xb + m * 64 + d8 * 8 + 4);
        *reinterpret_cast<uint4*>(As + m * KP + d8 * 8) = cvt8(f0, f1);
    }
#pragma unroll
    for (int t = 0; t < 2; ++t) {
        int u = tid + t * 256;
        int m = u >> 3, d8 = u & 7;
        float4 f0 = *reinterpret_cast<const float4*>(W + m * 64 + d8 * 8);
        float4 f1 = *reinterpret_cast<const float4*>(W + m * 64 + d8 * 8 + 4);
        *reinterpret_cast<uint4*>(Ws + m * KP + d8 * 8) = cvt8(f0, f1);
    }
    __syncthreads();

    const int warp = tid >> 5, lane = tid & 31;
    const int wm = warp >> 1, wn = warp & 1;   // m: 4x64, n: 2x32
    const unsigned aB = sptr(As), wB = sptr(Ws);

    float c[4][4][4] = {};
#pragma unroll
    for (int kk = 0; kk < 4; ++kk) {
        const int k0 = kk * 16;
        unsigned a[4][4], b[4][2];
#pragma unroll
        for (int mt = 0; mt < 4; ++mt)
            ldsm4(a[mt], a_addr(aB, wm * 64 + mt * 16, k0, lane));
#pragma unroll
        for (int p = 0; p < 2; ++p) {
            unsigned r[4];
            ldsm4(r, b_addr(wB, wn * 32 + p * 16, k0, lane));
            b[2*p][0] = r[0]; b[2*p][1] = r[1];
            b[2*p+1][0] = r[2]; b[2*p+1][1] = r[3];
        }
#pragma unroll
        for (int mt = 0; mt < 4; ++mt)
#pragma unroll
            for (int nt = 0; nt < 4; ++nt)
                hmma(c[mt][nt], a[mt], b[nt]);
    }

#pragma unroll
    for (int mt = 0; mt < 4; ++mt) {
        int rr = wm * 64 + mt * 16 + (lane >> 2);
#pragma unroll
        for (int nt = 0; nt < 4; ++nt) {
            int cc = wn * 32 + nt * 8 + 2 * (lane & 3);
            *reinterpret_cast<__half2*>(out + (r0 + rr) * 64 + cc) =
                __floats2half2_rn(c[mt][nt][0], c[mt][nt][1]);
            *reinterpret_cast<__half2*>(out + (r0 + rr + 8) * 64 + cc) =
                __floats2half2_rn(c[mt][nt][2], c[mt][nt][3]);
        }
    }
}

// ============================================================================
// 2) Pass 1: HMMA QK^T, cp.async double-buffered; samp in-kernel; per-row
//    log2-sum-exp (diag -> samp); stores P in fragment-native tile layout
//    with coalesced STG.128.
// ============================================================================
__global__ void __launch_bounds__(256, 2)
pass1_kernel()
{
    extern __shared__ __half dsm[];
    __half* qs  = dsm;
    __half* ks0 = dsm + TILEH;
    __half* ks1 = dsm + 2 * TILEH;
    __shared__ float sampS[128];
    __shared__ float rowsum[4 * 128];

    const int tid = threadIdx.x, warp = tid >> 5, lane = tid & 31;
    const int wm = warp >> 2, wn = warp & 3;          // m: 2x64, n: 4x32
    const int nh = blockIdx.y, n = nh >> 4, h = nh & 15;
    const int qblk = 15 - blockIdx.x;                 // longest blocks first
    const int q0 = qblk * 128;
    const size_t baseh = (size_t)n * LL * HH * DH + (size_t)h * DH;
    const size_t tribase = (size_t)nh * NTRI + (qblk * (qblk + 1)) / 2;
    const float S2 = S2c;

    // async prologue: q tile -> qs, ok tile 0 -> ks0, k tile (for samp) -> ks1
    cp_tile(qs,  g_qh  + baseh + (size_t)q0 * 1024, tid); CP_COMMIT();
    cp_tile(ks0, g_okh + baseh,                     tid); CP_COMMIT();
    cp_tile(ks1, g_kh  + baseh + (size_t)q0 * 1024, tid); CP_COMMIT();
    CP_WAIT0();
    __syncthreads();

    // samp energies for this block's 128 q rows (dot of q,k from smem)
    if (tid < 128) {
        const __half2* qr = reinterpret_cast<const __half2*>(qs  + tid * KP);
        const __half2* kr = reinterpret_cast<const __half2*>(ks1 + tid * KP);
        float s = 0.0f;
#pragma unroll
        for (int i = 0; i < 32; ++i) {
            float2 a = __half22float2(qr[i]);
            float2 b = __half22float2(kr[i]);
            s += a.x * b.x + a.y * b.y;
        }
        sampS[tid] = s;
        g_samp[nh * LL + q0 + tid] = s;
    }

    const unsigned qB = sptr(qs);
    float srun[4][2] = {};                            // [mt][row-half]

    for (int ct = 0; ct <= qblk; ++ct) {
        __syncthreads();      // prior reads of target buffer (incl. samp) complete
        if (ct + 1 <= qblk) { // prefetch next ok tile
            __half* nb = ((ct + 1) & 1) ? ks1 : ks0;
            cp_tile(nb, g_okh + baseh + (size_t)(ct + 1) * 128 * 1024, tid);
            CP_COMMIT();
            CP_WAIT1();       // current tile's group complete (newest may pend)
        } else {
            CP_WAIT0();
        }
        __syncthreads();

        const unsigned kB = sptr((ct & 1) ? ks1 : ks0);

        float c[4][4][4] = {};
#pragma unroll
        for (int kk = 0; kk < 4; ++kk) {
            const int k0 = kk * 16;
            unsigned a[4][4], b[4][2];
#pragma unroll
            for (int mt = 0; mt < 4; ++mt)
                ldsm4(a[mt], a_addr(qB, wm * 64 + mt * 16, k0, lane));
#pragma unroll
            for (int p = 0; p < 2; ++p) {
                unsigned r[4];
                ldsm4(r, b_addr(kB, wn * 32 + p * 16, k0, lane));
                b[2*p][0] = r[0]; b[2*p][1] = r[1];
                b[2*p+1][0] = r[2]; b[2*p+1][1] = r[3];
            }
#pragma unroll
            for (int mt = 0; mt < 4; ++mt)
#pragma unroll
                for (int nt = 0; nt < 4; ++nt)
                    hmma(c[mt][nt], a[mt], b[nt]);
        }

        const bool dt = (ct == qblk);
        // per-(warp,mt) slot = 512 halves; pk0 at lane*8, pk1 at +256
        __half* tb = g_P + (tribase + ct) * TILE16K + (size_t)(warp * 4) * 512 + lane * 8;
#pragma unroll
        for (int mt = 0; mt < 4; ++mt) {
            const int rA = wm * 64 + mt * 16 + (lane >> 2);   // local q row (c0,c1)
            const int rB = rA + 8;                            // local q row (c2,c3)
            unsigned pw[8];
#pragma unroll
            for (int nt = 0; nt < 4; ++nt) {
                const int cl = wn * 32 + nt * 8 + 2 * (lane & 3);   // local l col
                float p0 = ex2(c[mt][nt][0] * S2);
                float p1 = ex2(c[mt][nt][1] * S2);
                float p2 = ex2(c[mt][nt][2] * S2);
                float p3 = ex2(c[mt][nt][3] * S2);
                __half2 h01 = __floats2half2_rn(p0, p1);
                __half2 h23 = __floats2half2_rn(p2, p3);
                pw[nt * 2]     = *reinterpret_cast<unsigned*>(&h01);
                pw[nt * 2 + 1] = *reinterpret_cast<unsigned*>(&h23);
                if (dt) {
                    if (cl     < rA) srun[mt][0] += p0;
                    else if (cl     == rA) srun[mt][0] += ex2(sampS[rA] * S2);
                    if (cl + 1 < rA) srun[mt][0] += p1;
                    else if (cl + 1 == rA) srun[mt][0] += ex2(sampS[rA] * S2);
                    if (cl     < rB) srun[mt][1] += p2;
                    else if (cl     == rB) srun[mt][1] += ex2(sampS[rB] * S2);
                    if (cl + 1 < rB) srun[mt][1] += p3;
                    else if (cl + 1 == rB) srun[mt][1] += ex2(sampS[rB] * S2);
                } else {
                    srun[mt][0] += p0 + p1;
                    srun[mt][1] += p2 + p3;
                }
            }
            uint4 pk0 = make_uint4(pw[0], pw[1], pw[2], pw[3]);   // nt0,1
            uint4 pk1 = make_uint4(pw[4], pw[5], pw[6], pw[7]);   // nt2,3
            *reinterpret_cast<uint4*>(tb + mt * 512)       = pk0;
            *reinterpret_cast<uint4*>(tb + mt * 512 + 256) = pk1;
        }
    }

    // deterministic block reduction: lane-quad reduce, per-wn smem slot, final sum
#pragma unroll
    for (int mt = 0; mt < 4; ++mt)
#pragma unroll
        for (int hf = 0; hf < 2; ++hf) {
            float s = srun[mt][hf];
            s += __shfl_xor_sync(0xffffffffu, s, 1);
            s += __shfl_xor_sync(0xffffffffu, s, 2);
            if ((lane & 3) == 0)
                rowsum[wn * 128 + wm * 64 + mt * 16 + (lane >> 2) + hf * 8] = s;
        }
    __syncthreads();
    if (tid < 128) {
        float s = rowsum[tid] + rowsum[128 + tid] + rowsum[256 + tid] + rowsum[384 + tid];
        g_lse2[nh * LL + q0 + tid] = log2f(s);
    }
}

// ============================================================================
// 3) colsum[nh][l] = sum_{q>l} P[q,l] * 2^-lse2[q].
//    Mirror-reader of the fragment tile layout; fully coalesced LDG.128.
//    grid (16, NHB): block = column block lblk; streams tiles (qt, lblk).
// ============================================================================
__global__ void __launch_bounds__(256)
colsum_kernel()
{
    __shared__ float wS[LL];
    __shared__ float red[2 * 128];

    const int tid = threadIdx.x, warp = tid >> 5, lane = tid & 31;
    const int wm = warp >> 2, wn = warp & 3;
    const int nh = blockIdx.y;
    const int lblk = blockIdx.x;

    for (int i = tid; i < LL; i += 256) wS[i] = ex2(-g_lse2[nh * LL + i]);
    __syncthreads();

    float csum[4][2] = {};
    for (int qt = lblk; qt < 16; ++qt) {
        const __half* tb = g_P + ((size_t)nh * NTRI + (qt * (qt + 1)) / 2 + lblk) * TILE16K
                         + (size_t)(warp * 4) * 512 + lane * 8;
        const bool dt = (qt == lblk);
#pragma unroll
        for (int mt = 0; mt < 4; ++mt) {
            uint4 pk0 = *reinterpret_cast<const uint4*>(tb + mt * 512);
            uint4 pk1 = *reinterpret_cast<const uint4*>(tb + mt * 512 + 256);
            unsigned pw[8] = { pk0.x, pk0.y, pk0.z, pk0.w, pk1.x, pk1.y, pk1.z, pk1.w };
            const int rA = wm * 64 + mt * 16 + (lane >> 2);
            const int rB = rA + 8;
            const float wA = wS[qt * 128 + rA];
            const float wB = wS[qt * 128 + rB];
#pragma unroll
            for (int nt = 0; nt < 4; ++nt) {
                unsigned u01 = pw[nt * 2];
                unsigned u23 = pw[nt * 2 + 1];
                float2 f01 = __half22float2(*reinterpret_cast<__half2*>(&u01));
                float2 f23 = __half22float2(*reinterpret_cast<__half2*>(&u23));
                if (dt) {
                    const int cl = wn * 32 + nt * 8 + 2 * (lane & 3);
                    if (rA > cl)     csum[nt][0] += f01.x * wA;
                    if (rA > cl + 1) csum[nt][1] += f01.y * wA;
                    if (rB > cl)     csum[nt][0] += f23.x * wB;
                    if (rB > cl + 1) csum[nt][1] += f23.y * wB;
                } else {
                    csum[nt][0] += f01.x * wA + f23.x * wB;
                    csum[nt][1] += f01.y * wA + f23.y * wB;
                }
            }
        }
    }

    // reduce over rows: lanes sharing (lane&3) across lane>>2, then across wm
#pragma unroll
    for (int nt = 0; nt < 4; ++nt)
#pragma unroll
        for (int hf = 0; hf < 2; ++hf) {
            float s = csum[nt][hf];
            s += __shfl_xor_sync(0xffffffffu, s, 4);
            s += __shfl_xor_sync(0xffffffffu, s, 8);
            s += __shfl_xor_sync(0xffffffffu, s, 16);
            if ((lane >> 2) == 0)
                red[wm * 128 + wn * 32 + nt * 8 + 2 * (lane & 3) + hf] = s;
        }
    __syncthreads();
    if (tid < 128)
        g_colsum[nh * LL + lblk * 128 + tid] = red[tid] + red[128 + tid];
}

// ============================================================================
// 4) Combine: X[n,l,h,:] = diag_score * v + colsum * ov   (half in/out)
// ============================================================================
__global__ void __launch_bounds__(256)
combine_kernel()
{
    int u = blockIdx.x * 256 + threadIdx.x;          // unit of 8 halves
    int hidx = u >> 3;                                // (n*LL + l)*HH + h
    int h = hidx & 15;
    int nl = hidx >> 4;
    int l = nl & (LL - 1);
    int n = nl >> 11;
    int si = (n * HH + h) * LL + l;
    float dg = ex2(g_samp[si] * S2c - g_lse2[si]);
    float cs = g_colsum[si];

    uint4 v4 = *reinterpret_cast<const uint4*>(g_vh  + (size_t)u * 8);
    uint4 o4 = *reinterpret_cast<const uint4*>(g_ovh + (size_t)u * 8);
    __half2* vh = reinterpret_cast<__half2*>(&v4);
    __half2* oh = reinterpret_cast<__half2*>(&o4);
    __half2 r[4];
#pragma unroll
    for (int i = 0; i < 4; ++i) {
        float2 fv = __half22float2(vh[i]);
        float2 fo = __half22float2(oh[i]);
        r[i] = __floats2half2_rn(dg * fv.x + cs * fo.x, dg * fv.y + cs * fo.y);
    }
    *reinterpret_cast<uint4*>(g_Xh + (size_t)u * 8) = *reinterpret_cast<uint4*>(r);
}

// ============================================================================
// 5) FC: out = X @ fc_w^T + fc_b  (4096x1024x1024), fp16 HMMA, cp.async 2-stage
// ============================================================================
__global__ void __launch_bounds__(256, 2)
fc_kernel(const float* __restrict__ bias, float* __restrict__ out)
{
    extern __shared__ __half dsm[];
    __half* Ab[2] = { dsm,             dsm + 2 * TILEH };
    __half* Bb[2] = { dsm + TILEH,     dsm + 3 * TILEH };

    const int tid = threadIdx.x, warp = tid >> 5, lane = tid & 31;
    const int wm = warp >> 2, wn = warp & 3;          // m: 2x64, n: 4x32
    const int m0 = blockIdx.y * 128, j0 = blockIdx.x * 128;

    cp_tile(Ab[0], g_Xh  + (size_t)m0 * 1024, tid);
    cp_tile(Bb[0], g_fwh + (size_t)j0 * 1024, tid);
    CP_COMMIT();

    float c[4][4][4] = {};
    for (int it = 0; it < 16; ++it) {
        __syncthreads();
        if (it + 1 < 16) {
            int nb = (it + 1) & 1;
            cp_tile(Ab[nb], g_Xh  + (size_t)m0 * 1024 + (it + 1) * 64, tid);
            cp_tile(Bb[nb], g_fwh + (size_t)j0 * 1024 + (it + 1) * 64, tid);
            CP_COMMIT();
            CP_WAIT1();
        } else {
            CP_WAIT0();
        }
        __syncthreads();

        const unsigned aB = sptr(Ab[it & 1]), bB = sptr(Bb[it & 1]);
#pragma unroll
        for (int kk = 0; kk < 4; ++kk) {
            const int k0 = kk * 16;
            unsigned a[4][4], b[4][2];
#pragma unroll
            for (int mt = 0; mt < 4; ++mt)
                ldsm4(a[mt], a_addr(aB, wm * 64 + mt * 16, k0, lane));
#pragma unroll
            for (int p = 0; p < 2; ++p) {
                unsigned r[4];
                ldsm4(r, b_addr(bB, wn * 32 + p * 16, k0, lane));
                b[2*p][0] = r[0]; b[2*p][1] = r[1];
                b[2*p+1][0] = r[2]; b[2*p+1][1] = r[3];
            }
#pragma unroll
            for (int mt = 0; mt < 4; ++mt)
#pragma unroll
                for (int nt = 0; nt < 4; ++nt)
                    hmma(c[mt][nt], a[mt], b[nt]);
        }
    }

#pragma unroll
    for (int mt = 0; mt < 4; ++mt) {
        int rr = m0 + wm * 64 + mt * 16 + (lane >> 2);
#pragma unroll
        for (int nt = 0; nt < 4; ++nt) {
            int cc = j0 + wn * 32 + nt * 8 + 2 * (lane & 3);
            float2 bb = *reinterpret_cast<const float2*>(bias + cc);
            *reinterpret_cast<float2*>(out + (size_t)rr * 1024 + cc) =
                make_float2(c[mt][nt][0] + bb.x, c[mt][nt][1] + bb.y);
            *reinterpret_cast<float2*>(out + (size_t)(rr + 8) * 1024 + cc) =
                make_float2(c[mt][nt][2] + bb.x, c[mt][nt][3] + bb.y);
        }
    }
}

// ============================================================================
extern "C" void kernel_launch(void* const* d_in, const int* in_sizes, int n_in,
                              void* d_out, int out_size)
{
    const float* values        = (const float*)d_in[0];
    const float* keys          = (const float*)d_in[1];
    const float* query         = (const float*)d_in[2];
    const float* origin_values = (const float*)d_in[3];
    const float* origin_keys   = (const float*)d_in[4];
    const float* Wv            = (const float*)d_in[5];
    const float* Wk            = (const float*)d_in[6];
    const float* Wq            = (const float*)d_in[7];
    const float* fc_w          = (const float*)d_in[8];
    const float* fc_b          = (const float*)d_in[9];
    // d_in[10] = mask : causal-only for these shapes (HIST == L); computed analytically.
    float* out = (float*)d_out;

    const int smem_p1 = 3 * TILEH * (int)sizeof(__half);   // 55296 B
    const int smem_fc = 4 * TILEH * (int)sizeof(__half);   // 73728 B
    cudaFuncSetAttribute(pass1_kernel, cudaFuncAttributeMaxDynamicSharedMemorySize, smem_p1);
    cudaFuncSetAttribute(fc_kernel,    cudaFuncAttributeMaxDynamicSharedMemorySize, smem_fc);

    // 1) fused projections (5 tensors) + fc_w convert
    proj_kernel<<<dim3(256, 6), 256>>>(values, keys, query, origin_values, origin_keys,
                                       Wv, Wk, Wq, fc_w);

    // 2) row log2-sum-exp (diag replaced, samp in-kernel) + store P (tile layout)
    pass1_kernel<<<dim3(16, NHB), 256, smem_p1>>>();

    // 3) weighted column sums of stored scores (strictly below diagonal)
    colsum_kernel<<<dim3(16, NHB), 256>>>();

    // 4) combine samp + origin attention -> X (fp16)
    combine_kernel<<<NLD / 8 / 256, 256>>>();

    // 5) final linear layer (fp16 HMMA, fp32 out)
    fc_kernel<<<dim3(8, 32), 256, smem_fc>>>(fc_b, out);
}

// round 16
// speedup vs baseline: 1.3668x; 1.0244x over previous
#include <cuda_runtime.h>
#include <cuda_fp16.h>

// Problem constants
#define NB   2
#define LL   2048
#define DD   1024
#define HH   16
#define DH   64
#define NHB  (NB*HH)                  // 32
#define NLD  (NB*LL*DD)               // 4194304
#define KP   72                       // smem pitch in halves (144B rows: ldmatrix conflict-free)
#define TILEH (128*KP)                // halves per 128x64 smem tile
#define NTRI  136                     // 16*17/2 tiles per (n,h) triangle
#define TILE16K 16384                 // halves per 128x128 P tile (128*128)

// logits = energy / sqrt(1024); base-2: exp(x/32) = exp2(x * log2(e)/32)
__device__ __constant__ float S2c = 1.44269504088896340736f / 32.0f;

// ---------------- scratch (device globals; no allocations allowed) ----------------
__device__ __half g_vh [NLD];
__device__ __half g_kh [NLD];
__device__ __half g_qh [NLD];
__device__ __half g_ovh[NLD];
__device__ __half g_okh[NLD];
__device__ __half g_fwh[DD*DD];
__device__ __half g_Xh [NLD];
__device__ float  g_samp  [NHB*LL];
__device__ float  g_lse2  [NHB*LL];
// unnormalized scores P = exp2(e*S2), fp16, fragment-native tile layout,
// triangular tile packing: tile (qblk, ct) of head nh at
//   g_P + (nh*NTRI + qblk*(qblk+1)/2 + ct) * TILE16K
// within a tile: slot (warp*4 + mt) of 512 halves;
//   pk0 (nt0,1) at slot*512 + lane*8 ; pk1 (nt2,3) at slot*512 + 256 + lane*8
__device__ __half g_P[(size_t)NHB * NTRI * TILE16K];   // 142.6 MB

// ---------------- helpers ----------------
__device__ __forceinline__ unsigned sptr(const void* p) {
    return (unsigned)__cvta_generic_to_shared(p);
}
__device__ __forceinline__ void ldsm4(unsigned r[4], unsigned a) {
    asm volatile("ldmatrix.sync.aligned.m8n8.x4.shared.b16 {%0,%1,%2,%3}, [%4];"
        : "=r"(r[0]), "=r"(r[1]), "=r"(r[2]), "=r"(r[3]) : "r"(a));
}
__device__ __forceinline__ void hmma(float c[4], const unsigned a[4], const unsigned b[2]) {
    asm volatile("mma.sync.aligned.m16n8k16.row.col.f32.f16.f16.f32 "
        "{%0,%1,%2,%3},{%4,%5,%6,%7},{%8,%9},{%0,%1,%2,%3};"
        : "+f"(c[0]), "+f"(c[1]), "+f"(c[2]), "+f"(c[3])
        : "r"(a[0]), "r"(a[1]), "r"(a[2]), "r"(a[3]), "r"(b[0]), "r"(b[1]));
}
__device__ __forceinline__ uint4 cvt8(float4 f0, float4 f1) {
    __half2 h[4] = { __floats2half2_rn(f0.x, f0.y), __floats2half2_rn(f0.z, f0.w),
                     __floats2half2_rn(f1.x, f1.y), __floats2half2_rn(f1.z, f1.w) };
    return *reinterpret_cast<uint4*>(h);
}
__device__ __forceinline__ float ex2(float x) {
    float r; asm("ex2.approx.f32 %0, %1;" : "=f"(r) : "f"(x)); return r;
}
__device__ __forceinline__ void cpa16(__half* dst, const __half* src) {
    asm volatile("cp.async.cg.shared.global [%0], [%1], 16;"
        :: "r"(sptr(dst)), "l"(src));
}
#define CP_COMMIT() asm volatile("cp.async.commit_group;")
#define CP_WAIT0()  asm volatile("cp.async.wait_group 0;")
#define CP_WAIT1()  asm volatile("cp.async.wait_group 1;")
#define CP_WAIT2()  asm volatile("cp.async.wait_group 2;")

// streaming (evict-first) global access for the once-touched P tensor
__device__ __forceinline__ void stg_cs(void* p, uint4 v) {
    asm volatile("st.global.cs.v4.b32 [%0], {%1,%2,%3,%4};"
        :: "l"(p), "r"(v.x), "r"(v.y), "r"(v.z), "r"(v.w) : "memory");
}
__device__ __forceinline__ uint4 ldg_cs(const void* p) {
    uint4 v;
    asm volatile("ld.global.cs.v4.b32 {%0,%1,%2,%3}, [%4];"
        : "=r"(v.x), "=r"(v.y), "=r"(v.z), "=r"(v.w) : "l"(p));
    return v;
}

// cp.async a 128x64-half tile (global row stride 1024 halves) into [.][KP] smem
__device__ __forceinline__ void
cp_tile(__half* dst, const __half* src, int tid)
{
#pragma unroll
    for (int t = 0; t < 4; ++t) {
        int u = tid + t * 256;                 // 1024 units of 8 halves
        int m = u >> 3, d8 = u & 7;
        cpa16(dst + m * KP + d8 * 8, src + (size_t)m * 1024 + d8 * 8);
    }
}

// A-operand ldmatrix address for a 16x16 tile at (row0, k0) in [.][KP] smem
__device__ __forceinline__ unsigned a_addr(unsigned base, int row0, int k0, int lane) {
    return base + (unsigned)(((row0 + (lane & 15)) * KP + k0 + ((lane >> 4) << 3)) * 2);
}
// B-operand pair address (2 adjacent n-tiles = 16 n-rows) at (n0, k0)
__device__ __forceinline__ unsigned b_addr(unsigned base, int n0, int k0, int lane) {
    int g = lane & 7, sel = lane >> 3;
    return base + (unsigned)(((n0 + g + ((sel >> 1) << 3)) * KP + k0 + ((sel & 1) << 3)) * 2);
}

// ============================================================================
// 1) Fused projections + fc_w convert. grid (256, 6); block 256.
// ============================================================================
__global__ void __launch_bounds__(256)
proj_kernel(const float* __restrict__ v_in, const float* __restrict__ k_in,
            const float* __restrict__ q_in, const float* __restrict__ ov_in,
            const float* __restrict__ ok_in,
            const float* __restrict__ Wv, const float* __restrict__ Wk,
            const float* __restrict__ Wq, const float* __restrict__ fw)
{
    __shared__ __half As[256 * KP];
    __shared__ __half Ws[64 * KP];

    const int tid = threadIdx.x;
    if (blockIdx.y == 5) {                    // fc_w fp32 -> fp16
        int u0 = blockIdx.x * 512;
#pragma unroll
        for (int t = 0; t < 2; ++t) {
            int u = u0 + tid + t * 256;
            float4 f0 = *reinterpret_cast<const float4*>(fw + (size_t)u * 8);
            float4 f1 = *reinterpret_cast<const float4*>(fw + (size_t)u * 8 + 4);
            *reinterpret_cast<uint4*>(g_fwh + (size_t)u * 8) = cvt8(f0, f1);
        }
        return;
    }

    const float* X; const float* W; __half* out;
    switch (blockIdx.y) {
        case 0:  X = v_in;  W = Wv; out = g_vh;  break;
        case 1:  X = k_in;  W = Wk; out = g_kh;  break;
        case 2:  X = q_in;  W = Wq; out = g_qh;  break;
        case 3:  X = ov_in; W = Wv; out = g_ovh; break;
        default: X = ok_in; W = Wk; out = g_okh; break;
    }
    const size_t r0 = (size_t)blockIdx.x * 256;
    const float* Xb = X + r0 * 64;

#pragma unroll
    for (int t = 0; t < 8; ++t) {
        int u = tid + t * 256;
        int m = u >> 3, d8 = u & 7;
        float4 f0 = *reinterpret_cast<const float4*>(Xb + m * 64 + d8 * 8);
        float4 f1 = *reinterpret_cast<const float4*>(Xb + m * 64 + d8 * 8 + 4);
        *reinterpret_cast<uint4*>(As + m * KP + d8 * 8) = cvt8(f0, f1);
    }
#pragma unroll
    for (int t = 0; t < 2; ++t) {
        int u = tid + t * 256;
        int m = u >> 3, d8 = u & 7;
        float4 f0 = *reinterpret_cast<const float4*>(W + m * 64 + d8 * 8);
        float4 f1 = *reinterpret_cast<const float4*>(W + m * 64 + d8 * 8 + 4);
        *reinterpret_cast<uint4*>(Ws + m * KP + d8 * 8) = cvt8(f0, f1);
    }
    __syncthreads();

    const int warp = tid >> 5, lane = tid & 31;
    const int wm = warp >> 1, wn = warp & 1;   // m: 4x64, n: 2x32
    const unsigned aB = sptr(As), wB = sptr(Ws);

    float c[4][4][4] = {};
#pragma unroll
    for (int kk = 0; kk < 4; ++kk) {
        const int k0 = kk * 16;
        unsigned a[4][4], b[4][2];
#pragma unroll
        for (int mt = 0; mt < 4; ++mt)
            ldsm4(a[mt], a_addr(aB, wm * 64 + mt * 16, k0, lane));
#pragma unroll
        for (int p = 0; p < 2; ++p) {
            unsigned r[4];
            ldsm4(r, b_addr(wB, wn * 32 + p * 16, k0, lane));
            b[2*p][0] = r[0]; b[2*p][1] = r[1];
            b[2*p+1][0] = r[2]; b[2*p+1][1] = r[3];
        }
#pragma unroll
        for (int mt = 0; mt < 4; ++mt)
#pragma unroll
            for (int nt = 0; nt < 4; ++nt)
                hmma(c[mt][nt], a[mt], b[nt]);
    }

#pragma unroll
    for (int mt = 0; mt < 4; ++mt) {
        int rr = wm * 64 + mt * 16 + (lane >> 2);
#pragma unroll
        for (int nt = 0; nt < 4; ++nt) {
            int cc = wn * 32 + nt * 8 + 2 * (lane & 3);
            *reinterpret_cast<__half2*>(out + (r0 + rr) * 64 + cc) =
                __floats2half2_rn(c[mt][nt][0], c[mt][nt][1]);
            *reinterpret_cast<__half2*>(out + (r0 + rr + 8) * 64 + cc) =
                __floats2half2_rn(c[mt][nt][2], c[mt][nt][3]);
        }
    }
}

// ============================================================================
// 2) Pass 1: HMMA QK^T, 3-stage cp.async pipeline; samp in-kernel; per-row
//    log2-sum-exp (diag -> samp); stores P (fragment tile layout, .cs STG.128).
//    dynamic smem: qs + 3 rotating k-buffers = 4 * TILEH halves.
// ============================================================================
__global__ void __launch_bounds__(256, 2)
pass1_kernel()
{
    extern __shared__ __half dsm[];
    __half* qs = dsm;
    __half* ksb[3] = { dsm + TILEH, dsm + 2 * TILEH, dsm + 3 * TILEH };
    __shared__ float sampS[128];
    __shared__ float rowsum[4 * 128];

    const int tid = threadIdx.x, warp = tid >> 5, lane = tid & 31;
    const int wm = warp >> 2, wn = warp & 3;          // m: 2x64, n: 4x32
    const int nh = blockIdx.y, n = nh >> 4, h = nh & 15;
    const int qblk = 15 - blockIdx.x;                 // longest blocks first
    const int q0 = qblk * 128;
    const size_t baseh = (size_t)n * LL * HH * DH + (size_t)h * DH;
    const size_t tribase = (size_t)nh * NTRI + (qblk * (qblk + 1)) / 2;
    const float S2 = S2c;

    // async prologue (one group): q tile, ok tiles 0[,1], k tile (samp) -> ksb[2]
    cp_tile(qs,     g_qh  + baseh + (size_t)q0 * 1024, tid);
    cp_tile(ksb[0], g_okh + baseh,                     tid);
    if (qblk >= 1)
        cp_tile(ksb[1], g_okh + baseh + (size_t)128 * 1024, tid);
    cp_tile(ksb[2], g_kh  + baseh + (size_t)q0 * 1024, tid);
    CP_COMMIT();
    CP_WAIT0();
    __syncthreads();

    // samp energies for this block's 128 q rows (dot of q,k from smem)
    if (tid < 128) {
        const __half2* qr = reinterpret_cast<const __half2*>(qs     + tid * KP);
        const __half2* kr = reinterpret_cast<const __half2*>(ksb[2] + tid * KP);
        float s = 0.0f;
#pragma unroll
        for (int i = 0; i < 32; ++i) {
            float2 a = __half22float2(qr[i]);
            float2 b = __half22float2(kr[i]);
            s += a.x * b.x + a.y * b.y;
        }
        sampS[tid] = s;
        g_samp[nh * LL + q0 + tid] = s;
    }

    const unsigned qB = sptr(qs);
    float srun[4][2] = {};                            // [mt][row-half]

    for (int ct = 0; ct <= qblk; ++ct) {
        __syncthreads();      // prior reads of rotation target (incl. samp) done
        if (ct + 2 <= qblk) { // prefetch distance 2
            cp_tile(ksb[(ct + 2) % 3],
                    g_okh + baseh + (size_t)(ct + 2) * 128 * 1024, tid);
            CP_COMMIT();
            CP_WAIT2();       // tile ct's group (3rd newest) retired
        } else if (ct + 1 <= qblk) {
            CP_WAIT1();
        } else {
            CP_WAIT0();
        }
        __syncthreads();

        const unsigned kB = sptr(ksb[ct % 3]);

        float c[4][4][4] = {};
#pragma unroll
        for (int kk = 0; kk < 4; ++kk) {
            const int k0 = kk * 16;
            unsigned a[4][4], b[4][2];
#pragma unroll
            for (int mt = 0; mt < 4; ++mt)
                ldsm4(a[mt], a_addr(qB, wm * 64 + mt * 16, k0, lane));
#pragma unroll
            for (int p = 0; p < 2; ++p) {
                unsigned r[4];
                ldsm4(r, b_addr(kB, wn * 32 + p * 16, k0, lane));
                b[2*p][0] = r[0]; b[2*p][1] = r[1];
                b[2*p+1][0] = r[2]; b[2*p+1][1] = r[3];
            }
#pragma unroll
            for (int mt = 0; mt < 4; ++mt)
#pragma unroll
                for (int nt = 0; nt < 4; ++nt)
                    hmma(c[mt][nt], a[mt], b[nt]);
        }

        const bool dt = (ct == qblk);
        // per-(warp,mt) slot = 512 halves; pk0 at lane*8, pk1 at +256
        __half* tb = g_P + (tribase + ct) * TILE16K + (size_t)(warp * 4) * 512 + lane * 8;
#pragma unroll
        for (int mt = 0; mt < 4; ++mt) {
            const int rA = wm * 64 + mt * 16 + (lane >> 2);   // local q row (c0,c1)
            const int rB = rA + 8;                            // local q row (c2,c3)
            unsigned pw[8];
#pragma unroll
            for (int nt = 0; nt < 4; ++nt) {
                const int cl = wn * 32 + nt * 8 + 2 * (lane & 3);   // local l col
                float p0 = ex2(c[mt][nt][0] * S2);
                float p1 = ex2(c[mt][nt][1] * S2);
                float p2 = ex2(c[mt][nt][2] * S2);
                float p3 = ex2(c[mt][nt][3] * S2);
                __half2 h01 = __floats2half2_rn(p0, p1);
                __half2 h23 = __floats2half2_rn(p2, p3);
                pw[nt * 2]     = *reinterpret_cast<unsigned*>(&h01);
                pw[nt * 2 + 1] = *reinterpret_cast<unsigned*>(&h23);
                if (dt) {
                    if (cl     < rA) srun[mt][0] += p0;
                    else if (cl     == rA) srun[mt][0] += ex2(sampS[rA] * S2);
                    if (cl + 1 < rA) srun[mt][0] += p1;
                    else if (cl + 1 == rA) srun[mt][0] += ex2(sampS[rA] * S2);
                    if (cl     < rB) srun[mt][1] += p2;
                    else if (cl     == rB) srun[mt][1] += ex2(sampS[rB] * S2);
                    if (cl + 1 < rB) srun[mt][1] += p3;
                    else if (cl + 1 == rB) srun[mt][1] += ex2(sampS[rB] * S2);
                } else {
                    srun[mt][0] += p0 + p1;
                    srun[mt][1] += p2 + p3;
                }
            }
            stg_cs(tb + mt * 512,       make_uint4(pw[0], pw[1], pw[2], pw[3]));
            stg_cs(tb + mt * 512 + 256, make_uint4(pw[4], pw[5], pw[6], pw[7]));
        }
    }

    // deterministic block reduction: lane-quad reduce, per-wn smem slot, final sum
#pragma unroll
    for (int mt = 0; mt < 4; ++mt)
#pragma unroll
        for (int hf = 0; hf < 2; ++hf) {
            float s = srun[mt][hf];
            s += __shfl_xor_sync(0xffffffffu, s, 1);
            s += __shfl_xor_sync(0xffffffffu, s, 2);
            if ((lane & 3) == 0)
                rowsum[wn * 128 + wm * 64 + mt * 16 + (lane >> 2) + hf * 8] = s;
        }
    __syncthreads();
    if (tid < 128) {
        float s = rowsum[tid] + rowsum[128 + tid] + rowsum[256 + tid] + rowsum[384 + tid];
        g_lse2[nh * LL + q0 + tid] = log2f(s);
    }
}

// ============================================================================
// 3) Fused colsum + combine. Block (lblk, nh):
//    colsum[l] = sum_{q>l} P[q,l] * 2^-lse2[q]  (streams tiles, .cs LDG.128)
//    then X[n,l,h,:] = dg*v + colsum*ov for its 128 l's.
// ============================================================================
__global__ void __launch_bounds__(256)
colsum_kernel()
{
    __shared__ float wS[LL];
    __shared__ float red[2 * 128];
    __shared__ float csS[128];
    __shared__ float dgS[128];

    const int tid = threadIdx.x, warp = tid >> 5, lane = tid & 31;
    const int wm = warp >> 2, wn = warp & 3;
    const int nh = blockIdx.y, n = nh >> 4, h = nh & 15;
    const int lblk = blockIdx.x;

    for (int i = tid; i < LL; i += 256) wS[i] = ex2(-g_lse2[nh * LL + i]);
    __syncthreads();

    float csum[4][2] = {};
    for (int qt = lblk; qt < 16; ++qt) {
        const __half* tb = g_P + ((size_t)nh * NTRI + (qt * (qt + 1)) / 2 + lblk) * TILE16K
                         + (size_t)(warp * 4) * 512 + lane * 8;
        const bool dt = (qt == lblk);
#pragma unroll
        for (int mt = 0; mt < 4; ++mt) {
            uint4 pk0 = ldg_cs(tb + mt * 512);
            uint4 pk1 = ldg_cs(tb + mt * 512 + 256);
            unsigned pw[8] = { pk0.x, pk0.y, pk0.z, pk0.w, pk1.x, pk1.y, pk1.z, pk1.w };
            const int rA = wm * 64 + mt * 16 + (lane >> 2);
            const int rB = rA + 8;
            const float wA = wS[qt * 128 + rA];
            const float wB = wS[qt * 128 + rB];
#pragma unroll
            for (int nt = 0; nt < 4; ++nt) {
                unsigned u01 = pw[nt * 2];
                unsigned u23 = pw[nt * 2 + 1];
                float2 f01 = __half22float2(*reinterpret_cast<__half2*>(&u01));
                float2 f23 = __half22float2(*reinterpret_cast<__half2*>(&u23));
                if (dt) {
                    const int cl = wn * 32 + nt * 8 + 2 * (lane & 3);
                    if (rA > cl)     csum[nt][0] += f01.x * wA;
                    if (rA > cl + 1) csum[nt][1] += f01.y * wA;
                    if (rB > cl)     csum[nt][0] += f23.x * wB;
                    if (rB > cl + 1) csum[nt][1] += f23.y * wB;
                } else {
                    csum[nt][0] += f01.x * wA + f23.x * wB;
                    csum[nt][1] += f01.y * wA + f23.y * wB;
                }
            }
        }
    }

    // reduce over rows: lanes sharing (lane&3) across lane>>2, then across wm
#pragma unroll
    for (int nt = 0; nt < 4; ++nt)
#pragma unroll
        for (int hf = 0; hf < 2; ++hf) {
            float s = csum[nt][hf];
            s += __shfl_xor_sync(0xffffffffu, s, 4);
            s += __shfl_xor_sync(0xffffffffu, s, 8);
            s += __shfl_xor_sync(0xffffffffu, s, 16);
            if ((lane >> 2) == 0)
                red[wm * 128 + wn * 32 + nt * 8 + 2 * (lane & 3) + hf] = s;
        }
    __syncthreads();
    if (tid < 128) {
        int l = lblk * 128 + tid;
        csS[tid] = red[tid] + red[128 + tid];
        dgS[tid] = ex2(g_samp[nh * LL + l] * S2c) * wS[l];   // diag score
    }
    __syncthreads();

    // combine: X[n, l, h, :] = dg * v + cs * ov   for this block's 128 l's
#pragma unroll
    for (int t = 0; t < 4; ++t) {
        int u = tid + t * 256;                 // 1024 units of 8 halves
        int ll = u >> 3, d8 = u & 7;
        size_t row = ((size_t)(n * LL + lblk * 128 + ll) * HH + h);
        size_t addr = row * 64 + d8 * 8;
        float dg = dgS[ll], cs = csS[ll];
        uint4 v4 = *reinterpret_cast<const uint4*>(g_vh  + addr);
        uint4 o4 = *reinterpret_cast<const uint4*>(g_ovh + addr);
        __half2* vh = reinterpret_cast<__half2*>(&v4);
        __half2* oh = reinterpret_cast<__half2*>(&o4);
        __half2 r[4];
#pragma unroll
        for (int i = 0; i < 4; ++i) {
            float2 fv = __half22float2(vh[i]);
            float2 fo = __half22float2(oh[i]);
            r[i] = __floats2half2_rn(dg * fv.x + cs * fo.x, dg * fv.y + cs * fo.y);
        }
        *reinterpret_cast<uint4*>(g_Xh + addr) = *reinterpret_cast<uint4*>(r);
    }
}

// ============================================================================
// 4) FC: out = X @ fc_w^T + fc_b  (4096x1024x1024), fp16 HMMA, 3-stage cp.async
//    dynamic smem: 6 tiles = [A0,B0,A1,B1,A2,B2]
// ============================================================================
__global__ void __launch_bounds__(256, 2)
fc_kernel(const float* __restrict__ bias, float* __restrict__ out)
{
    extern __shared__ __half dsm[];

    const int tid = threadIdx.x, warp = tid >> 5, lane = tid & 31;
    const int wm = warp >> 2, wn = warp & 3;          // m: 2x64, n: 4x32
    const int m0 = blockIdx.y * 128, j0 = blockIdx.x * 128;

    // stages 0,1 (one group each: A+B pair)
#pragma unroll
    for (int s = 0; s < 2; ++s) {
        cp_tile(dsm + s * 2 * TILEH,         g_Xh  + (size_t)m0 * 1024 + s * 64, tid);
        cp_tile(dsm + s * 2 * TILEH + TILEH, g_fwh + (size_t)j0 * 1024 + s * 64, tid);
        CP_COMMIT();
    }

    float c[4][4][4] = {};
    for (int it = 0; it < 16; ++it) {
        __syncthreads();                 // reads of rotation target complete
        if (it + 2 < 16) {
            int nb = (it + 2) % 3;
            cp_tile(dsm + nb * 2 * TILEH,         g_Xh  + (size_t)m0 * 1024 + (it + 2) * 64, tid);
            cp_tile(dsm + nb * 2 * TILEH + TILEH, g_fwh + (size_t)j0 * 1024 + (it + 2) * 64, tid);
            CP_COMMIT();
            CP_WAIT2();
        } else if (it + 1 < 16) {
            CP_WAIT1();
        } else {
            CP_WAIT0();
        }
        __syncthreads();

        const int cb = it % 3;
        const unsigned aB = sptr(dsm + cb * 2 * TILEH);
        const unsigned bB = sptr(dsm + cb * 2 * TILEH + TILEH);
#pragma unroll
        for (int kk = 0; kk < 4; ++kk) {
            const int k0 = kk * 16;
            unsigned a[4][4], b[4][2];
#pragma unroll
            for (int mt = 0; mt < 4; ++mt)
                ldsm4(a[mt], a_addr(aB, wm * 64 + mt * 16, k0, lane));
#pragma unroll
            for (int p = 0; p < 2; ++p) {
                unsigned r[4];
                ldsm4(r, b_addr(bB, wn * 32 + p * 16, k0, lane));
                b[2*p][0] = r[0]; b[2*p][1] = r[1];
                b[2*p+1][0] = r[2]; b[2*p+1][1] = r[3];
            }
#pragma unroll
            for (int mt = 0; mt < 4; ++mt)
#pragma unroll
                for (int nt = 0; nt < 4; ++nt)
                    hmma(c[mt][nt], a[mt], b[nt]);
        }
    }

#pragma unroll
    for (int mt = 0; mt < 4; ++mt) {
        int rr = m0 + wm * 64 + mt * 16 + (lane >> 2);
#pragma unroll
        for (int nt = 0; nt < 4; ++nt) {
            int cc = j0 + wn * 32 + nt * 8 + 2 * (lane & 3);
            float2 bb = *reinterpret_cast<const float2*>(bias + cc);
            *reinterpret_cast<float2*>(out + (size_t)rr * 1024 + cc) =
                make_float2(c[mt][nt][0] + bb.x, c[mt][nt][1] + bb.y);
            *reinterpret_cast<float2*>(out + (size_t)(rr + 8) * 1024 + cc) =
                make_float2(c[mt][nt][2] + bb.x, c[mt][nt][3] + bb.y);
        }
    }
}

// ============================================================================
extern "C" void kernel_launch(void* const* d_in, const int* in_sizes, int n_in,
                              void* d_out, int out_size)
{
    const float* values        = (const float*)d_in[0];
    const float* keys          = (const float*)d_in[1];
    const float* query         = (const float*)d_in[2];
    const float* origin_values = (const float*)d_in[3];
    const float* origin_keys   = (const float*)d_in[4];
    const float* Wv            = (const float*)d_in[5];
    const float* Wk            = (const float*)d_in[6];
    const float* Wq            = (const float*)d_in[7];
    const float* fc_w          = (const float*)d_in[8];
    const float* fc_b          = (const float*)d_in[9];
    // d_in[10] = mask : causal-only for these shapes (HIST == L); computed analytically.
    float* out = (float*)d_out;

    const int smem_p1 = 4 * TILEH * (int)sizeof(__half);   // 73728 B
    const int smem_fc = 6 * TILEH * (int)sizeof(__half);   // 110592 B
    cudaFuncSetAttribute(pass1_kernel, cudaFuncAttributeMaxDynamicSharedMemorySize, smem_p1);
    cudaFuncSetAttribute(fc_kernel,    cudaFuncAttributeMaxDynamicSharedMemorySize, smem_fc);

    // 1) fused projections (5 tensors) + fc_w convert
    proj_kernel<<<dim3(256, 6), 256>>>(values, keys, query, origin_values, origin_keys,
                                       Wv, Wk, Wq, fc_w);

    // 2) row log2-sum-exp (diag replaced, samp in-kernel) + store P (tile layout)
    pass1_kernel<<<dim3(16, NHB), 256, smem_p1>>>();

    // 3) weighted column sums of stored scores + combine -> X (fp16)
    colsum_kernel<<<dim3(16, NHB), 256>>>();

    // 4) final linear layer (fp16 HMMA, fp32 out)
    fc_kernel<<<dim3(8, 32), 256, smem_fc>>>(fc_b, out);
}